// round 12
// baseline (speedup 1.0000x reference)
#include <cuda_runtime.h>
#include <cuda_bf16.h>
#include <math.h>
#include <stdint.h>

#define Bb 2
#define Ss 2048
#define Ee 1024
#define Hh 16
#define Dd 64
#define Mm (Bb*Ss)   // 4096

// Scratch (allocation-free rule: __device__ globals)
__device__ float g_v[Bb*Hh*Ss*Dd];
__device__ float g_cos[Ss*32];
__device__ float g_sin[Ss*32];
__device__ __nv_bfloat16 g_xh3[3*Mm*Ee];
__device__ __nv_bfloat16 g_xl3[3*Mm*Ee];
__device__ __nv_bfloat16 g_wh4[4*Ee*Ee];
__device__ __nv_bfloat16 g_wl4[4*Ee*Ee];
__device__ __nv_bfloat16 g_qh[Bb*Hh*Ss*Dd];
__device__ __nv_bfloat16 g_ql[Bb*Hh*Ss*Dd];
__device__ __nv_bfloat16 g_kh[Bb*Hh*Ss*Dd];
__device__ __nv_bfloat16 g_kl[Bb*Hh*Ss*Dd];
__device__ __nv_bfloat16 g_vth[Bb*Hh*Dd*Ss];
__device__ __nv_bfloat16 g_vtl[Bb*Hh*Dd*Ss];

// ---------------------------------------------------------------------------
// Helpers (plain sm_80-class PTX only: mma.sync / ldmatrix / cp.async)
// ---------------------------------------------------------------------------
__device__ __forceinline__ uint32_t smem_to_u32(const void* p) {
    uint32_t a;
    asm("{ .reg .u64 t; cvta.to.shared.u64 t, %1; cvt.u32.u64 %0, t; }" : "=r"(a) : "l"(p));
    return a;
}
#define CP_ASYNC16(dst, src) \
    asm volatile("cp.async.cg.shared.global [%0], [%1], 16;" :: "r"(dst), "l"(src))
#define CP_ASYNC_COMMIT() asm volatile("cp.async.commit_group;" ::: "memory")
#define CP_ASYNC_WAIT0()  asm volatile("cp.async.wait_group 0;" ::: "memory")
#define CP_ASYNC_WAIT1()  asm volatile("cp.async.wait_group 1;" ::: "memory")
#define SWZ128(o) ((o) ^ (((o) >> 3) & 0x70))

#define LDSM4(r, addr) \
    asm volatile("ldmatrix.sync.aligned.m8n8.x4.shared.b16 {%0,%1,%2,%3}, [%4];" \
        : "=r"((r)[0]), "=r"((r)[1]), "=r"((r)[2]), "=r"((r)[3]) : "r"(addr))

#define MMA16816(c, a, b0, b1) \
    asm volatile("mma.sync.aligned.m16n8k16.row.col.f32.bf16.bf16.f32 " \
        "{%0,%1,%2,%3},{%4,%5,%6,%7},{%8,%9},{%0,%1,%2,%3};" \
        : "+f"((c)[0]), "+f"((c)[1]), "+f"((c)[2]), "+f"((c)[3]) \
        : "r"((a)[0]), "r"((a)[1]), "r"((a)[2]), "r"((a)[3]), "r"(b0), "r"(b1))

__device__ __forceinline__ uint32_t bf2pack(float lo, float hi) {
    uint32_t r;
    asm("cvt.rn.bf16x2.f32 %0, %1, %2;" : "=r"(r) : "f"(hi), "f"(lo));
    return r;
}

// split a packed pair into hi + lo bf16x2
__device__ __forceinline__ void split2(float a, float b, uint32_t& h, uint32_t& l) {
    h = bf2pack(a, b);
    float f0 = __uint_as_float(h << 16), f1 = __uint_as_float(h & 0xFFFF0000u);
    l = bf2pack(a - f0, b - f1);
}

// fast e^x on FMA pipe
__device__ __forceinline__ float fexp(float x) {
    x = fmaxf(x, -87.0f);
    float z = x * 1.4426950408889634f;
    float t = z + 12582912.0f;
    float n = t - 12582912.0f;
    float f = z - n;
    float p = 1.3333558146e-3f;
    p = fmaf(p, f, 9.6181291907e-3f);
    p = fmaf(p, f, 5.5504108664e-2f);
    p = fmaf(p, f, 2.4022650696e-1f);
    p = fmaf(p, f, 6.9314718056e-1f);
    p = fmaf(p, f, 1.0f);
    float sc = __uint_as_float((__float_as_uint(t) << 23) + 0x3F800000u);
    return p * sc;
}

// ---------------------------------------------------------------------------
// Batched splits
// ---------------------------------------------------------------------------
__global__ __launch_bounds__(256)
void split3_kernel(const float* __restrict__ s0, const float* __restrict__ s1,
                   const float* __restrict__ s2, __nv_bfloat16* __restrict__ hi,
                   __nv_bfloat16* __restrict__ lo, int elems4)
{
    int z = blockIdx.y;
    const float* x = (z == 0) ? s0 : (z == 1) ? s1 : s2;
    int i = blockIdx.x * 256 + threadIdx.x;
    float4 v = ((const float4*)x)[i];
    uint32_t h01, l01, h23, l23;
    split2(v.x, v.y, h01, l01);
    split2(v.z, v.w, h23, l23);
    ((uint2*)hi)[(size_t)z * elems4 + i] = make_uint2(h01, h23);
    ((uint2*)lo)[(size_t)z * elems4 + i] = make_uint2(l01, l23);
}

__global__ __launch_bounds__(256)
void split4W_kernel(const float* __restrict__ s0, const float* __restrict__ s1,
                    const float* __restrict__ s2, const float* __restrict__ s3,
                    __nv_bfloat16* __restrict__ hi, __nv_bfloat16* __restrict__ lo,
                    int elems4)
{
    int z = blockIdx.y;
    const float* x = (z == 0) ? s0 : (z == 1) ? s1 : (z == 2) ? s2 : s3;
    int i = blockIdx.x * 256 + threadIdx.x;
    float4 v = ((const float4*)x)[i];
    uint32_t h01, l01, h23, l23;
    split2(v.x, v.y, h01, l01);
    split2(v.z, v.w, h23, l23);
    ((uint2*)hi)[(size_t)z * elems4 + i] = make_uint2(h01, h23);
    ((uint2*)lo)[(size_t)z * elems4 + i] = make_uint2(l01, l23);
}

// ---------------------------------------------------------------------------
// HMMA GEMM body, 2-stage software pipeline.
// CTA tile 256x128, 512 threads (16 warps, 8m x 2n; warp tile 32x64).
// K-chunk 64 (SW128). Stage = 96KB, 2 stages = 192KB, 1 CTA/SM.
// mode 0: fp32 row-major + bias  (O projection)
// mode 1: fp32 scatter [B,H,S,D] + bias  (V)
// mode 2: bias + RoPE + bf16-split scatter [B,H,S,D]  (Q, K)
// ---------------------------------------------------------------------------
#define TG_STAGE   98304u
#define TG_SMEM    196608

__device__ __forceinline__
void tgemm_body(uint32_t sb, const __nv_bfloat16* Ahp, const __nv_bfloat16* Alp,
                const __nv_bfloat16* Bhp, const __nv_bfloat16* Blp,
                const float* bias, float* outf,
                __nv_bfloat16* dh, __nv_bfloat16* dl,
                const float* ct, const float* st,
                int mode, int m0, int n0)
{
    const int tid = threadIdx.x;
    const int lane = tid & 31, wid = tid >> 5;
    const int wm = (wid >> 1) * 32, wn = (wid & 1) * 64;

    float acc[2][8][4];
    #pragma unroll
    for (int mt = 0; mt < 2; mt++)
        #pragma unroll
        for (int nt = 0; nt < 8; nt++)
            #pragma unroll
            for (int r = 0; r < 4; r++) acc[mt][nt][r] = 0.f;

    const int lr = lane & 15;
    const uint32_t akb = (lane >> 4) * 16;
    const uint32_t xrA = (uint32_t)(lr & 7) << 4;
    const int brow = (lane & 7) + ((lane >> 1) & 8);
    const uint32_t bkb = (uint32_t)(lane & 8) * 2;
    const uint32_t xrB = (uint32_t)(lane & 7) << 4;

    uint32_t aoff[2], boff[4];
    #pragma unroll
    for (int mt = 0; mt < 2; mt++) aoff[mt] = (uint32_t)(wm + mt * 16 + lr) * 128;
    #pragma unroll
    for (int p = 0; p < 4; p++)    boff[p]  = (uint32_t)(wn + p * 16 + brow) * 128;

    // stage fill: A (256x128B hi+lo) + B (128x128B hi+lo), 12 cp.async/thread
    auto fill = [&](int kc, uint32_t stb) {
        #pragma unroll
        for (int i = 0; i < 4; i++) {
            int p = i * 512 + tid;
            int r = p >> 3, c = (p & 7) * 16;
            uint32_t o = SWZ128((uint32_t)(r * 128 + c));
            size_t go = (size_t)(m0 + r) * 2048 + kc * 128 + c;
            CP_ASYNC16(stb + o,          (const char*)Ahp + go);
            CP_ASYNC16(stb + 32768 + o,  (const char*)Alp + go);
        }
        #pragma unroll
        for (int i = 0; i < 2; i++) {
            int p = i * 512 + tid;
            int r = p >> 3, c = (p & 7) * 16;
            uint32_t o = SWZ128((uint32_t)(r * 128 + c));
            size_t go = (size_t)(n0 + r) * 2048 + kc * 128 + c;
            CP_ASYNC16(stb + 65536 + o,  (const char*)Bhp + go);
            CP_ASYNC16(stb + 81920 + o,  (const char*)Blp + go);
        }
        CP_ASYNC_COMMIT();
    };

    fill(0, sb);

    for (int kc = 0; kc < 16; kc++) {
        __syncthreads();                       // all warps past compute(kc-1)
        if (kc < 15) {
            fill(kc + 1, sb + (uint32_t)((kc + 1) & 1) * TG_STAGE);
            CP_ASYNC_WAIT1();                  // f(kc) done, f(kc+1) in flight
        } else {
            CP_ASYNC_WAIT0();
        }
        __syncthreads();                       // fill(kc) visible to all

        const uint32_t base = sb + (uint32_t)(kc & 1) * TG_STAGE;
        const uint32_t sA  = base,          sAl = base + 32768;
        const uint32_t sB  = base + 65536,  sBl = base + 81920;

        #pragma unroll
        for (int s = 0; s < 4; s++) {
            const uint32_t kA = ((uint32_t)(s * 32) + akb) ^ xrA;
            const uint32_t kB = ((uint32_t)(s * 32) + bkb) ^ xrB;

            uint32_t ah[2][4], bh[4][4];
            #pragma unroll
            for (int mt = 0; mt < 2; mt++) LDSM4(ah[mt], sA + aoff[mt] + kA);
            #pragma unroll
            for (int p = 0; p < 4; p++)    LDSM4(bh[p],  sB + boff[p] + kB);

            #pragma unroll
            for (int mt = 0; mt < 2; mt++)
                #pragma unroll
                for (int nt = 0; nt < 8; nt++)
                    MMA16816(acc[mt][nt], ah[mt], bh[nt>>1][(nt&1)*2], bh[nt>>1][(nt&1)*2+1]);

            {
                uint32_t al[2][4];
                #pragma unroll
                for (int mt = 0; mt < 2; mt++) LDSM4(al[mt], sAl + aoff[mt] + kA);
                #pragma unroll
                for (int mt = 0; mt < 2; mt++)
                    #pragma unroll
                    for (int nt = 0; nt < 8; nt++)
                        MMA16816(acc[mt][nt], al[mt], bh[nt>>1][(nt&1)*2], bh[nt>>1][(nt&1)*2+1]);
            }
            {
                uint32_t bl[4][4];
                #pragma unroll
                for (int p = 0; p < 4; p++) LDSM4(bl[p], sBl + boff[p] + kB);
                #pragma unroll
                for (int mt = 0; mt < 2; mt++)
                    #pragma unroll
                    for (int nt = 0; nt < 8; nt++)
                        MMA16816(acc[mt][nt], ah[mt], bl[nt>>1][(nt&1)*2], bl[nt>>1][(nt&1)*2+1]);
            }
        }
    }

    const int g = lane >> 2, t = (lane & 3) * 2;

    if (mode == 2) {
        // bias + RoPE + split-bf16 scatter to [B,H,S,D]
        const int hh = (n0 + wn) >> 6;
        #pragma unroll
        for (int mt = 0; mt < 2; mt++) {
            #pragma unroll
            for (int nt = 0; nt < 4; nt++) {
                const int j = nt * 8 + t;            // pair index 0..31 (even)
                float b1a = bias[hh*64 + j],      b1b = bias[hh*64 + j + 1];
                float b2a = bias[hh*64 + j + 32], b2b = bias[hh*64 + j + 33];
                #pragma unroll
                for (int rr = 0; rr < 2; rr++) {
                    int m = m0 + wm + mt * 16 + g + rr * 8;
                    int b = m >> 11, s = m & 2047;
                    float2 cs = *(const float2*)(ct + s * 32 + j);
                    float2 sn = *(const float2*)(st + s * 32 + j);
                    float x1a = acc[mt][nt][rr*2]     + b1a;
                    float x1b = acc[mt][nt][rr*2+1]   + b1b;
                    float x2a = acc[mt][nt+4][rr*2]   + b2a;
                    float x2b = acc[mt][nt+4][rr*2+1] + b2b;
                    float r1a = x1a*cs.x - x2a*sn.x, r2a = x2a*cs.x + x1a*sn.x;
                    float r1b = x1b*cs.y - x2b*sn.y, r2b = x2b*cs.y + x1b*sn.y;
                    uint32_t h1, l1, h2, l2;
                    split2(r1a, r1b, h1, l1);
                    split2(r2a, r2b, h2, l2);
                    size_t base = ((size_t)(b * Hh + hh) * Ss + s) * Dd;
                    *(uint32_t*)(dh + base + j)      = h1;
                    *(uint32_t*)(dl + base + j)      = l1;
                    *(uint32_t*)(dh + base + j + 32) = h2;
                    *(uint32_t*)(dl + base + j + 32) = l2;
                }
            }
        }
    } else {
        #pragma unroll
        for (int mt = 0; mt < 2; mt++) {
            #pragma unroll
            for (int nt = 0; nt < 8; nt++) {
                int m = m0 + wm + mt * 16 + g;
                int n = n0 + wn + nt * 8 + t;
                float b0v = bias[n], b1v = bias[n + 1];
                #pragma unroll
                for (int rr = 0; rr < 2; rr++) {
                    int mr = m + rr * 8;
                    float2 val = make_float2(acc[mt][nt][rr*2] + b0v,
                                             acc[mt][nt][rr*2+1] + b1v);
                    float* dst;
                    if (mode == 0) {
                        dst = outf + (size_t)mr * Ee + n;
                    } else {
                        int b = mr >> 11, s = mr & 2047;
                        int h = n >> 6, d0 = n & 63;
                        dst = outf + (((size_t)(b * Hh + h) * Ss) + s) * Dd + d0;
                    }
                    *(float2*)dst = val;
                }
            }
        }
    }
}

// Fused QKV projection: z=0 Q (rope+split), z=1 K (rope+split), z=2 V (fp32).
__global__ __launch_bounds__(512, 1)
void tgemm_qkv(const float* __restrict__ bq, const float* __restrict__ bk,
               const float* __restrict__ bv, float* __restrict__ vp,
               const float* __restrict__ ct, const float* __restrict__ st)
{
    extern __shared__ char smem[];
    uint32_t sb = smem_to_u32(smem);
    const int z = blockIdx.z;
    const size_t xo = (size_t)z * Mm * Ee, wo = (size_t)z * Ee * Ee;
    const float* bias = (z == 0) ? bq : (z == 1) ? bk : bv;
    __nv_bfloat16* dh = (z == 0) ? g_qh : g_kh;
    __nv_bfloat16* dl = (z == 0) ? g_ql : g_kl;
    tgemm_body(sb, g_xh3 + xo, g_xl3 + xo, g_wh4 + wo, g_wl4 + wo,
               bias, vp, dh, dl, ct, st,
               (z == 2) ? 1 : 2, blockIdx.y * 256, blockIdx.x * 128);
}

// O projection: X from slot 0 (written by flash), W from slot 3.
__global__ __launch_bounds__(512, 1)
void tgemm_o(const float* __restrict__ bias, float* __restrict__ out)
{
    extern __shared__ char smem[];
    uint32_t sb = smem_to_u32(smem);
    tgemm_body(sb, g_xh3, g_xl3, g_wh4 + (size_t)3 * Ee * Ee,
               g_wl4 + (size_t)3 * Ee * Ee,
               bias, out, nullptr, nullptr, nullptr, nullptr,
               0, blockIdx.y * 256, blockIdx.x * 128);
}

// ---------------------------------------------------------------------------
// RoPE table
// ---------------------------------------------------------------------------
__global__ __launch_bounds__(256)
void rope_table_kernel(float* __restrict__ cosT, float* __restrict__ sinT)
{
    int idx = blockIdx.x * 256 + threadIdx.x;
    int j = idx & 31;
    int s = idx >> 5;
    double inv = exp(-((double)(2 * j) / 64.0) * log(10000.0));
    double sd, cd;
    sincos((double)s * inv, &sd, &cd);
    cosT[idx] = (float)cd;
    sinT[idx] = (float)sd;
}

// ---------------------------------------------------------------------------
// V convert: fp32 [B,H,S,D] -> split bf16 transposed [B,H,D,S]
// ---------------------------------------------------------------------------
__global__ __launch_bounds__(256)
void vconvert(const float* __restrict__ v, __nv_bfloat16* __restrict__ vth,
              __nv_bfloat16* __restrict__ vtl)
{
    __shared__ float sm[64][65];
    const int s0 = blockIdx.x * 64, bh = blockIdx.y;
    const int tid = threadIdx.x;
    const float* src = v + ((size_t)bh * Ss + s0) * Dd;
    #pragma unroll
    for (int i = 0; i < 16; i++) {
        int p = tid + i * 256;
        int r = p >> 6, c = p & 63;
        sm[c][r] = src[(size_t)r * Dd + c];
    }
    __syncthreads();
    #pragma unroll
    for (int i = 0; i < 8; i++) {
        int pp = tid + i * 256;
        int d = pp >> 5, sp = (pp & 31) * 2;
        uint32_t hp, lp;
        split2(sm[d][sp], sm[d][sp + 1], hp, lp);
        size_t off = ((size_t)(bh * Dd + d)) * Ss + s0 + sp;
        *(uint32_t*)(vth + off) = hp;
        *(uint32_t*)(vtl + off) = lp;
    }
}

// ---------------------------------------------------------------------------
// Flash attention, HMMA bf16 3-term split, causal. Epilogue writes split bf16
// directly into the O-projection input buffers (g_xh3/g_xl3 slot 0).
// ---------------------------------------------------------------------------
#define FL_SMEM 65536

__global__ __launch_bounds__(256)
void flash_mma(const __nv_bfloat16* __restrict__ qhp, const __nv_bfloat16* __restrict__ qlp,
               const __nv_bfloat16* __restrict__ khp, const __nv_bfloat16* __restrict__ klp,
               const __nv_bfloat16* __restrict__ vthp, const __nv_bfloat16* __restrict__ vtlp,
               __nv_bfloat16* __restrict__ xh, __nv_bfloat16* __restrict__ xl)
{
    extern __shared__ char smem[];
    uint32_t sb = smem_to_u32(smem);
    const uint32_t sQh = sb,          sQl = sb + 16384;
    const uint32_t sKh = sb + 32768,  sKl = sb + 40960;
    const uint32_t sVh = sb + 49152,  sVl = sb + 57344;

    const int tid = threadIdx.x, lane = tid & 31, wid = tid >> 5;
    const int qt = (int)gridDim.x - 1 - (int)blockIdx.x;   // heavy tiles first
    const int bh = blockIdx.y;
    const int q0 = qt * 128;
    const int wm = wid * 16;

    {
        const char* gq  = (const char*)qhp + ((size_t)(bh * Ss + q0)) * 128;
        const char* gql = (const char*)qlp + ((size_t)(bh * Ss + q0)) * 128;
        #pragma unroll
        for (int i = 0; i < 4; i++) {
            int p = i * 256 + tid;
            int r = p >> 3, c = (p & 7) * 16;
            uint32_t o1 = SWZ128((uint32_t)(r * 128 + c));
            CP_ASYNC16(sQh + o1, gq  + (size_t)r * 128 + c);
            CP_ASYNC16(sQl + o1, gql + (size_t)r * 128 + c);
        }
        CP_ASYNC_COMMIT(); CP_ASYNC_WAIT0();
    }
    __syncthreads();

    const uint32_t xr  = (uint32_t)(lane & 7) << 4;
    const uint32_t akb = (uint32_t)(lane >> 4) * 16;
    const uint32_t arow = (uint32_t)(wm + (lane & 15)) * 128;
    uint32_t aQh[4][4], aQl[4][4];
    #pragma unroll
    for (int s = 0; s < 4; s++) {
        uint32_t kA = ((uint32_t)(s * 32) + akb) ^ xr;
        LDSM4(aQh[s], sQh + arow + kA);
        LDSM4(aQl[s], sQl + arow + kA);
    }

    const int brow = (lane & 7) + ((lane >> 1) & 8);
    const uint32_t bkb = (uint32_t)(lane & 8) * 2;
    uint32_t boffs[4];
    #pragma unroll
    for (int p = 0; p < 4; p++) boffs[p] = (uint32_t)(p * 16 + brow) * 128;

    float o[8][4];
    #pragma unroll
    for (int nt = 0; nt < 8; nt++)
        #pragma unroll
        for (int r = 0; r < 4; r++) o[nt][r] = 0.f;
    float mv[2] = {-1e30f, -1e30f}, lv[2] = {0.f, 0.f};

    const int g = lane >> 2, tq = (lane & 3) * 2;
    const int ntiles = 2 * qt + 2;

    for (int it = 0; it < ntiles; it++) {
        const int kv0 = it * 64;
        __syncthreads();
        {
            const char* gkh = (const char*)khp  + ((size_t)(bh * Ss + kv0)) * 128;
            const char* gkl = (const char*)klp  + ((size_t)(bh * Ss + kv0)) * 128;
            const char* gvh = (const char*)vthp + (((size_t)bh * Dd) * Ss + kv0) * 2;
            const char* gvl = (const char*)vtlp + (((size_t)bh * Dd) * Ss + kv0) * 2;
            #pragma unroll
            for (int i = 0; i < 2; i++) {
                int p = i * 256 + tid;
                int r = p >> 3, c = (p & 7) * 16;
                uint32_t o1 = SWZ128((uint32_t)(r * 128 + c));
                CP_ASYNC16(sKh + o1, gkh + (size_t)r * 128 + c);
                CP_ASYNC16(sKl + o1, gkl + (size_t)r * 128 + c);
                CP_ASYNC16(sVh + o1, gvh + (size_t)r * (Ss * 2) + c);
                CP_ASYNC16(sVl + o1, gvl + (size_t)r * (Ss * 2) + c);
            }
            CP_ASYNC_COMMIT(); CP_ASYNC_WAIT0();
        }
        __syncthreads();

        float acc[8][4];
        #pragma unroll
        for (int nt = 0; nt < 8; nt++)
            #pragma unroll
            for (int r = 0; r < 4; r++) acc[nt][r] = 0.f;

        #pragma unroll
        for (int s = 0; s < 4; s++) {
            uint32_t kB = ((uint32_t)(s * 32) + bkb) ^ xr;
            uint32_t bKh[4][4], bKl[4][4];
            #pragma unroll
            for (int p = 0; p < 4; p++) LDSM4(bKh[p], sKh + boffs[p] + kB);
            #pragma unroll
            for (int p = 0; p < 4; p++) LDSM4(bKl[p], sKl + boffs[p] + kB);
            #pragma unroll
            for (int p = 0; p < 4; p++) {
                MMA16816(acc[2*p],   aQh[s], bKh[p][0], bKh[p][1]);
                MMA16816(acc[2*p+1], aQh[s], bKh[p][2], bKh[p][3]);
                MMA16816(acc[2*p],   aQl[s], bKh[p][0], bKh[p][1]);
                MMA16816(acc[2*p+1], aQl[s], bKh[p][2], bKh[p][3]);
                MMA16816(acc[2*p],   aQh[s], bKl[p][0], bKl[p][1]);
                MMA16816(acc[2*p+1], aQh[s], bKl[p][2], bKl[p][3]);
            }
        }

        const int row0 = q0 + wm + g;
        if (it >= 2 * qt) {
            #pragma unroll
            for (int nt = 0; nt < 8; nt++) {
                int col = kv0 + nt * 8 + tq;
                #pragma unroll
                for (int r = 0; r < 4; r++) {
                    int cc = col + (r & 1);
                    int rr = row0 + (r >= 2 ? 8 : 0);
                    acc[nt][r] = (cc > rr) ? -1e30f : acc[nt][r] * 0.125f;
                }
            }
        } else {
            #pragma unroll
            for (int nt = 0; nt < 8; nt++)
                #pragma unroll
                for (int r = 0; r < 4; r++) acc[nt][r] *= 0.125f;
        }

        #pragma unroll
        for (int h = 0; h < 2; h++) {
            float rmax = -1e30f;
            #pragma unroll
            for (int nt = 0; nt < 8; nt++)
                rmax = fmaxf(rmax, fmaxf(acc[nt][2*h], acc[nt][2*h+1]));
            rmax = fmaxf(rmax, __shfl_xor_sync(0xffffffffu, rmax, 1));
            rmax = fmaxf(rmax, __shfl_xor_sync(0xffffffffu, rmax, 2));
            float mnew = fmaxf(mv[h], rmax);
            float fac = fexp(mv[h] - mnew);
            float rs = 0.f;
            #pragma unroll
            for (int nt = 0; nt < 8; nt++) {
                acc[nt][2*h]   = fexp(acc[nt][2*h]   - mnew);
                acc[nt][2*h+1] = fexp(acc[nt][2*h+1] - mnew);
                rs += acc[nt][2*h] + acc[nt][2*h+1];
            }
            rs += __shfl_xor_sync(0xffffffffu, rs, 1);
            rs += __shfl_xor_sync(0xffffffffu, rs, 2);
            lv[h] = lv[h] * fac + rs;
            mv[h] = mnew;
            #pragma unroll
            for (int nt = 0; nt < 8; nt++) { o[nt][2*h] *= fac; o[nt][2*h+1] *= fac; }
        }

        uint32_t aPh[4][4], aPl[4][4];
        #pragma unroll
        for (int ks = 0; ks < 4; ks++) {
            #pragma unroll
            for (int half = 0; half < 2; half++) {
                int nt = 2 * ks + half;
                #pragma unroll
                for (int rp = 0; rp < 2; rp++) {
                    uint32_t hp, lp;
                    split2(acc[nt][2*rp], acc[nt][2*rp+1], hp, lp);
                    aPh[ks][half*2 + rp] = hp;
                    aPl[ks][half*2 + rp] = lp;
                }
            }
        }

        #pragma unroll
        for (int s = 0; s < 4; s++) {
            uint32_t kB = ((uint32_t)(s * 32) + bkb) ^ xr;
            uint32_t bVh[4][4], bVl[4][4];
            #pragma unroll
            for (int p = 0; p < 4; p++) LDSM4(bVh[p], sVh + boffs[p] + kB);
            #pragma unroll
            for (int p = 0; p < 4; p++) LDSM4(bVl[p], sVl + boffs[p] + kB);
            #pragma unroll
            for (int p = 0; p < 4; p++) {
                MMA16816(o[2*p],   aPh[s], bVh[p][0], bVh[p][1]);
                MMA16816(o[2*p+1], aPh[s], bVh[p][2], bVh[p][3]);
                MMA16816(o[2*p],   aPl[s], bVh[p][0], bVh[p][1]);
                MMA16816(o[2*p+1], aPl[s], bVh[p][2], bVh[p][3]);
                MMA16816(o[2*p],   aPh[s], bVl[p][0], bVl[p][1]);
                MMA16816(o[2*p+1], aPh[s], bVl[p][2], bVl[p][3]);
            }
        }
    }

    // epilogue: normalize + split-bf16 into O-projection input [M, E]
    const int b = bh >> 4, h = bh & 15;
    float il0 = 1.0f / lv[0], il1 = 1.0f / lv[1];
    const int row0 = q0 + wm + g;
    #pragma unroll
    for (int nt = 0; nt < 8; nt++) {
        int col = h * 64 + nt * 8 + tq;
        uint32_t hp, lp;
        size_t i0 = (size_t)(b * Ss + row0) * Ee + col;
        split2(o[nt][0] * il0, o[nt][1] * il0, hp, lp);
        *(uint32_t*)(xh + i0) = hp;
        *(uint32_t*)(xl + i0) = lp;
        size_t i1 = (size_t)(b * Ss + row0 + 8) * Ee + col;
        split2(o[nt][2] * il1, o[nt][3] * il1, hp, lp);
        *(uint32_t*)(xh + i1) = hp;
        *(uint32_t*)(xl + i1) = lp;
    }
}

// ---------------------------------------------------------------------------
extern "C" void kernel_launch(void* const* d_in, const int* in_sizes, int n_in,
                              void* d_out, int out_size)
{
    (void)in_sizes; (void)n_in; (void)out_size;
    const float* query = (const float*)d_in[0];
    const float* key   = (const float*)d_in[1];
    const float* value = (const float*)d_in[2];
    const float* Wq = (const float*)d_in[3];
    const float* bq = (const float*)d_in[4];
    const float* Wk = (const float*)d_in[5];
    const float* bk = (const float*)d_in[6];
    const float* Wv = (const float*)d_in[7];
    const float* bv = (const float*)d_in[8];
    const float* Wo = (const float*)d_in[9];
    const float* bo = (const float*)d_in[10];
    float* out = (float*)d_out;

    float *vp, *ct, *st;
    __nv_bfloat16 *xh, *xl, *wh, *wl, *qh, *ql, *kh, *kl, *vth, *vtl;
    cudaGetSymbolAddress((void**)&vp,  g_v);
    cudaGetSymbolAddress((void**)&ct,  g_cos);
    cudaGetSymbolAddress((void**)&st,  g_sin);
    cudaGetSymbolAddress((void**)&xh,  g_xh3);
    cudaGetSymbolAddress((void**)&xl,  g_xl3);
    cudaGetSymbolAddress((void**)&wh,  g_wh4);
    cudaGetSymbolAddress((void**)&wl,  g_wl4);
    cudaGetSymbolAddress((void**)&qh,  g_qh);
    cudaGetSymbolAddress((void**)&ql,  g_ql);
    cudaGetSymbolAddress((void**)&kh,  g_kh);
    cudaGetSymbolAddress((void**)&kl,  g_kl);
    cudaGetSymbolAddress((void**)&vth, g_vth);
    cudaGetSymbolAddress((void**)&vtl, g_vtl);

    cudaFuncSetAttribute(tgemm_qkv,
                         cudaFuncAttributeMaxDynamicSharedMemorySize, TG_SMEM);
    cudaFuncSetAttribute(tgemm_o,
                         cudaFuncAttributeMaxDynamicSharedMemorySize, TG_SMEM);
    cudaFuncSetAttribute(flash_mma,
                         cudaFuncAttributeMaxDynamicSharedMemorySize, FL_SMEM);

    const int WBLK = (Ee * Ee / 4) / 256;   // 1024
    const int XBLK = (Mm * Ee / 4) / 256;   // 4096

    rope_table_kernel<<<(Ss * 32) / 256, 256>>>(ct, st);

    split3_kernel<<<dim3(XBLK, 3), 256>>>(query, key, value, xh, xl, Mm * Ee / 4);
    split4W_kernel<<<dim3(WBLK, 4), 256>>>(Wq, Wk, Wv, Wo, wh, wl, Ee * Ee / 4);

    // fused QKV projection (Q,K: +RoPE+split epilogue; V: fp32)
    tgemm_qkv<<<dim3(Ee / 128, Mm / 256, 3), 512, TG_SMEM>>>(bq, bk, bv, vp, ct, st);

    vconvert<<<dim3(Ss / 64, Bb * Hh), 256>>>(vp, vth, vtl);

    // flash writes split bf16 straight into O-projection input (slot 0)
    flash_mma<<<dim3(Ss / 128, Bb * Hh), 256, FL_SMEM>>>(qh, ql, kh, kl, vth, vtl, xh, xl);

    tgemm_o<<<dim3(Ee / 128, Mm / 256), 512, TG_SMEM>>>(bo, out);
}

// round 13
// speedup vs baseline: 1.3759x; 1.3759x over previous
#include <cuda_runtime.h>
#include <cuda_fp16.h>
#include <math.h>
#include <stdint.h>

#define Bb 2
#define Ss 2048
#define Ee 1024
#define Hh 16
#define Dd 64
#define Mm (Bb*Ss)   // 4096

// Scratch (allocation-free rule: __device__ globals)
__device__ float g_v[Bb*Hh*Ss*Dd];
__device__ float g_cos[Ss*32];
__device__ float g_sin[Ss*32];
__device__ __half g_xh3[3*Mm*Ee];
__device__ __half g_xl3[3*Mm*Ee];
__device__ __half g_wh4[4*Ee*Ee];
__device__ __half g_qh[Bb*Hh*Ss*Dd];
__device__ __half g_ql[Bb*Hh*Ss*Dd];
__device__ __half g_kh[Bb*Hh*Ss*Dd];
__device__ __half g_vth[Bb*Hh*Dd*Ss];

// ---------------------------------------------------------------------------
// Helpers (plain sm_80-class PTX only: mma.sync / ldmatrix / cp.async)
// ---------------------------------------------------------------------------
__device__ __forceinline__ uint32_t smem_to_u32(const void* p) {
    uint32_t a;
    asm("{ .reg .u64 t; cvta.to.shared.u64 t, %1; cvt.u32.u64 %0, t; }" : "=r"(a) : "l"(p));
    return a;
}
#define CP_ASYNC16(dst, src) \
    asm volatile("cp.async.cg.shared.global [%0], [%1], 16;" :: "r"(dst), "l"(src))
#define CP_ASYNC_COMMIT() asm volatile("cp.async.commit_group;" ::: "memory")
#define CP_ASYNC_WAIT0()  asm volatile("cp.async.wait_group 0;" ::: "memory")
#define SWZ128(o) ((o) ^ (((o) >> 3) & 0x70))

#define LDSM4(r, addr) \
    asm volatile("ldmatrix.sync.aligned.m8n8.x4.shared.b16 {%0,%1,%2,%3}, [%4];" \
        : "=r"((r)[0]), "=r"((r)[1]), "=r"((r)[2]), "=r"((r)[3]) : "r"(addr))

#define MMA16816(c, a, b0, b1) \
    asm volatile("mma.sync.aligned.m16n8k16.row.col.f32.f16.f16.f32 " \
        "{%0,%1,%2,%3},{%4,%5,%6,%7},{%8,%9},{%0,%1,%2,%3};" \
        : "+f"((c)[0]), "+f"((c)[1]), "+f"((c)[2]), "+f"((c)[3]) \
        : "r"((a)[0]), "r"((a)[1]), "r"((a)[2]), "r"((a)[3]), "r"(b0), "r"(b1))

__device__ __forceinline__ uint32_t h2u(__half2 h) {
    uint32_t u;
    u = *reinterpret_cast<uint32_t*>(&h);
    return u;
}
__device__ __forceinline__ uint32_t f16pack(float a, float b) {
    __half2 h = __floats2half2_rn(a, b);
    return h2u(h);
}
// split pair into fp16 hi + fp16 lo residual
__device__ __forceinline__ void split2(float a, float b, uint32_t& h, uint32_t& l) {
    __half2 hh = __floats2half2_rn(a, b);
    float fa = __half2float(__low2half(hh)), fb = __half2float(__high2half(hh));
    __half2 ll = __floats2half2_rn(a - fa, b - fb);
    h = h2u(hh);
    l = h2u(ll);
}

// fast e^x on FMA pipe
__device__ __forceinline__ float fexp(float x) {
    x = fmaxf(x, -87.0f);
    float z = x * 1.4426950408889634f;
    float t = z + 12582912.0f;
    float n = t - 12582912.0f;
    float f = z - n;
    float p = 1.3333558146e-3f;
    p = fmaf(p, f, 9.6181291907e-3f);
    p = fmaf(p, f, 5.5504108664e-2f);
    p = fmaf(p, f, 2.4022650696e-1f);
    p = fmaf(p, f, 6.9314718056e-1f);
    p = fmaf(p, f, 1.0f);
    float sc = __uint_as_float((__float_as_uint(t) << 23) + 0x3F800000u);
    return p * sc;
}

// ---------------------------------------------------------------------------
// Batched splits / rounds
// ---------------------------------------------------------------------------
__global__ __launch_bounds__(256)
void split3_kernel(const float* __restrict__ s0, const float* __restrict__ s1,
                   const float* __restrict__ s2, __half* __restrict__ hi,
                   __half* __restrict__ lo, int elems4)
{
    int z = blockIdx.y;
    const float* x = (z == 0) ? s0 : (z == 1) ? s1 : s2;
    int i = blockIdx.x * 256 + threadIdx.x;
    float4 v = ((const float4*)x)[i];
    uint32_t h01, l01, h23, l23;
    split2(v.x, v.y, h01, l01);
    split2(v.z, v.w, h23, l23);
    ((uint2*)hi)[(size_t)z * elems4 + i] = make_uint2(h01, h23);
    ((uint2*)lo)[(size_t)z * elems4 + i] = make_uint2(l01, l23);
}

// round 4 weight matrices to single fp16
__global__ __launch_bounds__(256)
void round4W_kernel(const float* __restrict__ s0, const float* __restrict__ s1,
                    const float* __restrict__ s2, const float* __restrict__ s3,
                    __half* __restrict__ hi, int elems4)
{
    int z = blockIdx.y;
    const float* x = (z == 0) ? s0 : (z == 1) ? s1 : (z == 2) ? s2 : s3;
    int i = blockIdx.x * 256 + threadIdx.x;
    float4 v = ((const float4*)x)[i];
    ((uint2*)hi)[(size_t)z * elems4 + i] =
        make_uint2(f16pack(v.x, v.y), f16pack(v.z, v.w));
}

// ---------------------------------------------------------------------------
// HMMA GEMM body, fp16 2-term (A split hi+lo, B single fp16).
// Single-stage, K-chunk 64 (SW128), 256 threads, 8 warps 4m x 2n (warp 32x64).
// smem 48KB -> up to 4 CTAs/SM.
// mode 0: fp32 row-major + bias  (O projection)
// mode 1: fp32 scatter [B,H,S,D] + bias  (V)
// mode 2: bias + RoPE + fp16 scatter [B,H,S,D]  (Q: hi+lo, K: hi only)
// ---------------------------------------------------------------------------
#define TG_SMEM 49152

__device__ __forceinline__
void tgemm_body(uint32_t sb, const __half* Ahp, const __half* Alp,
                const __half* Bhp,
                const float* bias, float* outf,
                __half* dh, __half* dl,
                const float* ct, const float* st,
                int mode, int m0, int n0)
{
    const int tid = threadIdx.x;
    const int lane = tid & 31, wid = tid >> 5;
    const int wm = (wid >> 1) * 32, wn = (wid & 1) * 64;

    const uint32_t sA  = sb;
    const uint32_t sAl = sb + 16384;
    const uint32_t sB  = sb + 32768;

    float acc[2][8][4];
    #pragma unroll
    for (int mt = 0; mt < 2; mt++)
        #pragma unroll
        for (int nt = 0; nt < 8; nt++)
            #pragma unroll
            for (int r = 0; r < 4; r++) acc[mt][nt][r] = 0.f;

    const int lr = lane & 15;
    const uint32_t akb = (lane >> 4) * 16;
    const uint32_t xrA = (uint32_t)(lr & 7) << 4;
    const int brow = (lane & 7) + ((lane >> 1) & 8);
    const uint32_t bkb = (uint32_t)(lane & 8) * 2;
    const uint32_t xrB = (uint32_t)(lane & 7) << 4;

    uint32_t aoff[2], boff[4];
    #pragma unroll
    for (int mt = 0; mt < 2; mt++) aoff[mt] = (uint32_t)(wm + mt * 16 + lr) * 128;
    #pragma unroll
    for (int p = 0; p < 4; p++)    boff[p]  = (uint32_t)(wn + p * 16 + brow) * 128;

    const char* srcs[3] = {(const char*)Ahp, (const char*)Alp, (const char*)Bhp};
    const uint32_t dsts[3] = {sA, sAl, sB};
    const int r0s[3] = {m0, m0, n0};

    for (int kc = 0; kc < 16; kc++) {
        if (kc) __syncthreads();
        #pragma unroll
        for (int arr = 0; arr < 3; arr++) {
            #pragma unroll
            for (int i = 0; i < 4; i++) {
                int p = i * 256 + tid;
                int r = p >> 3, c = (p & 7) * 16;
                uint32_t dst = dsts[arr] + SWZ128((uint32_t)(r * 128 + c));
                const char* src = srcs[arr] + ((size_t)(r0s[arr] + r)) * 2048
                                  + kc * 128 + c;
                CP_ASYNC16(dst, src);
            }
        }
        CP_ASYNC_COMMIT();
        CP_ASYNC_WAIT0();
        __syncthreads();

        #pragma unroll
        for (int s = 0; s < 4; s++) {
            const uint32_t kA = ((uint32_t)(s * 32) + akb) ^ xrA;
            const uint32_t kB = ((uint32_t)(s * 32) + bkb) ^ xrB;

            uint32_t ah[2][4], al[2][4], bh[4][4];
            #pragma unroll
            for (int mt = 0; mt < 2; mt++) LDSM4(ah[mt], sA  + aoff[mt] + kA);
            #pragma unroll
            for (int mt = 0; mt < 2; mt++) LDSM4(al[mt], sAl + aoff[mt] + kA);
            #pragma unroll
            for (int p = 0; p < 4; p++)    LDSM4(bh[p],  sB  + boff[p] + kB);

            #pragma unroll
            for (int mt = 0; mt < 2; mt++)
                #pragma unroll
                for (int nt = 0; nt < 8; nt++) {
                    MMA16816(acc[mt][nt], ah[mt], bh[nt>>1][(nt&1)*2], bh[nt>>1][(nt&1)*2+1]);
                    MMA16816(acc[mt][nt], al[mt], bh[nt>>1][(nt&1)*2], bh[nt>>1][(nt&1)*2+1]);
                }
        }
    }

    const int g = lane >> 2, t = (lane & 3) * 2;

    if (mode == 2) {
        // bias + RoPE + fp16 scatter to [B,H,S,D]; lo only if dl != nullptr
        const int hh = (n0 + wn) >> 6;
        #pragma unroll
        for (int mt = 0; mt < 2; mt++) {
            #pragma unroll
            for (int nt = 0; nt < 4; nt++) {
                const int j = nt * 8 + t;            // pair index 0..31 (even)
                float b1a = bias[hh*64 + j],      b1b = bias[hh*64 + j + 1];
                float b2a = bias[hh*64 + j + 32], b2b = bias[hh*64 + j + 33];
                #pragma unroll
                for (int rr = 0; rr < 2; rr++) {
                    int m = m0 + wm + mt * 16 + g + rr * 8;
                    int b = m >> 11, s = m & 2047;
                    float2 cs = *(const float2*)(ct + s * 32 + j);
                    float2 sn = *(const float2*)(st + s * 32 + j);
                    float x1a = acc[mt][nt][rr*2]     + b1a;
                    float x1b = acc[mt][nt][rr*2+1]   + b1b;
                    float x2a = acc[mt][nt+4][rr*2]   + b2a;
                    float x2b = acc[mt][nt+4][rr*2+1] + b2b;
                    float r1a = x1a*cs.x - x2a*sn.x, r2a = x2a*cs.x + x1a*sn.x;
                    float r1b = x1b*cs.y - x2b*sn.y, r2b = x2b*cs.y + x1b*sn.y;
                    size_t base = ((size_t)(b * Hh + hh) * Ss + s) * Dd;
                    if (dl) {
                        uint32_t h1, l1, h2, l2;
                        split2(r1a, r1b, h1, l1);
                        split2(r2a, r2b, h2, l2);
                        *(uint32_t*)(dh + base + j)      = h1;
                        *(uint32_t*)(dl + base + j)      = l1;
                        *(uint32_t*)(dh + base + j + 32) = h2;
                        *(uint32_t*)(dl + base + j + 32) = l2;
                    } else {
                        *(uint32_t*)(dh + base + j)      = f16pack(r1a, r1b);
                        *(uint32_t*)(dh + base + j + 32) = f16pack(r2a, r2b);
                    }
                }
            }
        }
    } else {
        #pragma unroll
        for (int mt = 0; mt < 2; mt++) {
            #pragma unroll
            for (int nt = 0; nt < 8; nt++) {
                int m = m0 + wm + mt * 16 + g;
                int n = n0 + wn + nt * 8 + t;
                float b0v = bias[n], b1v = bias[n + 1];
                #pragma unroll
                for (int rr = 0; rr < 2; rr++) {
                    int mr = m + rr * 8;
                    float2 val = make_float2(acc[mt][nt][rr*2] + b0v,
                                             acc[mt][nt][rr*2+1] + b1v);
                    float* dst;
                    if (mode == 0) {
                        dst = outf + (size_t)mr * Ee + n;
                    } else {
                        int b = mr >> 11, s = mr & 2047;
                        int h = n >> 6, d0 = n & 63;
                        dst = outf + (((size_t)(b * Hh + h) * Ss) + s) * Dd + d0;
                    }
                    *(float2*)dst = val;
                }
            }
        }
    }
}

// Fused QKV projection: z=0 Q (rope+split), z=1 K (rope, hi only), z=2 V (fp32).
__global__ __launch_bounds__(256, 2)
void tgemm_qkv(const float* __restrict__ bq, const float* __restrict__ bk,
               const float* __restrict__ bv, float* __restrict__ vp,
               const float* __restrict__ ct, const float* __restrict__ st)
{
    extern __shared__ char smem[];
    uint32_t sb = smem_to_u32(smem);
    const int z = blockIdx.z;
    const size_t xo = (size_t)z * Mm * Ee, wo = (size_t)z * Ee * Ee;
    const float* bias = (z == 0) ? bq : (z == 1) ? bk : bv;
    __half* dh = (z == 0) ? g_qh : g_kh;
    __half* dl = (z == 0) ? g_ql : nullptr;
    tgemm_body(sb, g_xh3 + xo, g_xl3 + xo, g_wh4 + wo,
               bias, vp, dh, dl, ct, st,
               (z == 2) ? 1 : 2, blockIdx.y * 128, blockIdx.x * 128);
}

// O projection: X from slot 0 (written by flash), W from slot 3.
__global__ __launch_bounds__(256, 2)
void tgemm_o(const float* __restrict__ bias, float* __restrict__ out)
{
    extern __shared__ char smem[];
    uint32_t sb = smem_to_u32(smem);
    tgemm_body(sb, g_xh3, g_xl3, g_wh4 + (size_t)3 * Ee * Ee,
               bias, out, nullptr, nullptr, nullptr, nullptr,
               0, blockIdx.y * 128, blockIdx.x * 128);
}

// ---------------------------------------------------------------------------
// RoPE table
// ---------------------------------------------------------------------------
__global__ __launch_bounds__(256)
void rope_table_kernel(float* __restrict__ cosT, float* __restrict__ sinT)
{
    int idx = blockIdx.x * 256 + threadIdx.x;
    int j = idx & 31;
    int s = idx >> 5;
    double inv = exp(-((double)(2 * j) / 64.0) * log(10000.0));
    double sd, cd;
    sincos((double)s * inv, &sd, &cd);
    cosT[idx] = (float)cd;
    sinT[idx] = (float)sd;
}

// ---------------------------------------------------------------------------
// V convert: fp32 [B,H,S,D] -> single fp16 transposed [B,H,D,S]
// ---------------------------------------------------------------------------
__global__ __launch_bounds__(256)
void vconvert(const float* __restrict__ v, __half* __restrict__ vth)
{
    __shared__ float sm[64][65];
    const int s0 = blockIdx.x * 64, bh = blockIdx.y;
    const int tid = threadIdx.x;
    const float* src = v + ((size_t)bh * Ss + s0) * Dd;
    #pragma unroll
    for (int i = 0; i < 16; i++) {
        int p = tid + i * 256;
        int r = p >> 6, c = p & 63;
        sm[c][r] = src[(size_t)r * Dd + c];
    }
    __syncthreads();
    #pragma unroll
    for (int i = 0; i < 8; i++) {
        int pp = tid + i * 256;
        int d = pp >> 5, sp = (pp & 31) * 2;
        size_t off = ((size_t)(bh * Dd + d)) * Ss + s0 + sp;
        *(uint32_t*)(vth + off) = f16pack(sm[d][sp], sm[d][sp + 1]);
    }
}

// ---------------------------------------------------------------------------
// Flash attention, fp16 2-term (Q split, K/V single; P split, V single).
// Block = 128 q rows, 8 warps (warp m16 x n64). KV tile 64. smem 48KB.
// Epilogue writes split fp16 into O-projection input (g_xh3/g_xl3 slot 0).
// ---------------------------------------------------------------------------
#define FL_SMEM 49152

__global__ __launch_bounds__(256)
void flash_mma(const __half* __restrict__ qhp, const __half* __restrict__ qlp,
               const __half* __restrict__ khp, const __half* __restrict__ vthp,
               __half* __restrict__ xh, __half* __restrict__ xl)
{
    extern __shared__ char smem[];
    uint32_t sb = smem_to_u32(smem);
    const uint32_t sQh = sb,          sQl = sb + 16384;
    const uint32_t sK  = sb + 32768,  sV  = sb + 40960;

    const int tid = threadIdx.x, lane = tid & 31, wid = tid >> 5;
    const int qt = (int)gridDim.x - 1 - (int)blockIdx.x;   // heavy tiles first
    const int bh = blockIdx.y;
    const int q0 = qt * 128;
    const int wm = wid * 16;

    {
        const char* gq  = (const char*)qhp + ((size_t)(bh * Ss + q0)) * 128;
        const char* gql = (const char*)qlp + ((size_t)(bh * Ss + q0)) * 128;
        #pragma unroll
        for (int i = 0; i < 4; i++) {
            int p = i * 256 + tid;
            int r = p >> 3, c = (p & 7) * 16;
            uint32_t o1 = SWZ128((uint32_t)(r * 128 + c));
            CP_ASYNC16(sQh + o1, gq  + (size_t)r * 128 + c);
            CP_ASYNC16(sQl + o1, gql + (size_t)r * 128 + c);
        }
        CP_ASYNC_COMMIT(); CP_ASYNC_WAIT0();
    }
    __syncthreads();

    const uint32_t xr  = (uint32_t)(lane & 7) << 4;
    const uint32_t akb = (uint32_t)(lane >> 4) * 16;
    const uint32_t arow = (uint32_t)(wm + (lane & 15)) * 128;
    uint32_t aQh[4][4], aQl[4][4];
    #pragma unroll
    for (int s = 0; s < 4; s++) {
        uint32_t kA = ((uint32_t)(s * 32) + akb) ^ xr;
        LDSM4(aQh[s], sQh + arow + kA);
        LDSM4(aQl[s], sQl + arow + kA);
    }

    const int brow = (lane & 7) + ((lane >> 1) & 8);
    const uint32_t bkb = (uint32_t)(lane & 8) * 2;
    uint32_t boffs[4];
    #pragma unroll
    for (int p = 0; p < 4; p++) boffs[p] = (uint32_t)(p * 16 + brow) * 128;

    float o[8][4];
    #pragma unroll
    for (int nt = 0; nt < 8; nt++)
        #pragma unroll
        for (int r = 0; r < 4; r++) o[nt][r] = 0.f;
    float mv[2] = {-1e30f, -1e30f}, lv[2] = {0.f, 0.f};

    const int g = lane >> 2, tq = (lane & 3) * 2;
    const int ntiles = 2 * qt + 2;

    for (int it = 0; it < ntiles; it++) {
        const int kv0 = it * 64;
        __syncthreads();
        {
            const char* gk = (const char*)khp  + ((size_t)(bh * Ss + kv0)) * 128;
            const char* gv = (const char*)vthp + (((size_t)bh * Dd) * Ss + kv0) * 2;
            #pragma unroll
            for (int i = 0; i < 2; i++) {
                int p = i * 256 + tid;
                int r = p >> 3, c = (p & 7) * 16;
                uint32_t o1 = SWZ128((uint32_t)(r * 128 + c));
                CP_ASYNC16(sK + o1, gk + (size_t)r * 128 + c);
                CP_ASYNC16(sV + o1, gv + (size_t)r * (Ss * 2) + c);
            }
            CP_ASYNC_COMMIT(); CP_ASYNC_WAIT0();
        }
        __syncthreads();

        float acc[8][4];
        #pragma unroll
        for (int nt = 0; nt < 8; nt++)
            #pragma unroll
            for (int r = 0; r < 4; r++) acc[nt][r] = 0.f;

        #pragma unroll
        for (int s = 0; s < 4; s++) {
            uint32_t kB = ((uint32_t)(s * 32) + bkb) ^ xr;
            uint32_t bK[4][4];
            #pragma unroll
            for (int p = 0; p < 4; p++) LDSM4(bK[p], sK + boffs[p] + kB);
            #pragma unroll
            for (int p = 0; p < 4; p++) {
                MMA16816(acc[2*p],   aQh[s], bK[p][0], bK[p][1]);
                MMA16816(acc[2*p+1], aQh[s], bK[p][2], bK[p][3]);
                MMA16816(acc[2*p],   aQl[s], bK[p][0], bK[p][1]);
                MMA16816(acc[2*p+1], aQl[s], bK[p][2], bK[p][3]);
            }
        }

        const int row0 = q0 + wm + g;
        if (it >= 2 * qt) {
            #pragma unroll
            for (int nt = 0; nt < 8; nt++) {
                int col = kv0 + nt * 8 + tq;
                #pragma unroll
                for (int r = 0; r < 4; r++) {
                    int cc = col + (r & 1);
                    int rr = row0 + (r >= 2 ? 8 : 0);
                    acc[nt][r] = (cc > rr) ? -1e30f : acc[nt][r] * 0.125f;
                }
            }
        } else {
            #pragma unroll
            for (int nt = 0; nt < 8; nt++)
                #pragma unroll
                for (int r = 0; r < 4; r++) acc[nt][r] *= 0.125f;
        }

        #pragma unroll
        for (int h = 0; h < 2; h++) {
            float rmax = -1e30f;
            #pragma unroll
            for (int nt = 0; nt < 8; nt++)
                rmax = fmaxf(rmax, fmaxf(acc[nt][2*h], acc[nt][2*h+1]));
            rmax = fmaxf(rmax, __shfl_xor_sync(0xffffffffu, rmax, 1));
            rmax = fmaxf(rmax, __shfl_xor_sync(0xffffffffu, rmax, 2));
            float mnew = fmaxf(mv[h], rmax);
            float fac = fexp(mv[h] - mnew);
            float rs = 0.f;
            #pragma unroll
            for (int nt = 0; nt < 8; nt++) {
                acc[nt][2*h]   = fexp(acc[nt][2*h]   - mnew);
                acc[nt][2*h+1] = fexp(acc[nt][2*h+1] - mnew);
                rs += acc[nt][2*h] + acc[nt][2*h+1];
            }
            rs += __shfl_xor_sync(0xffffffffu, rs, 1);
            rs += __shfl_xor_sync(0xffffffffu, rs, 2);
            lv[h] = lv[h] * fac + rs;
            mv[h] = mnew;
            #pragma unroll
            for (int nt = 0; nt < 8; nt++) { o[nt][2*h] *= fac; o[nt][2*h+1] *= fac; }
        }

        uint32_t aPh[4][4], aPl[4][4];
        #pragma unroll
        for (int ks = 0; ks < 4; ks++) {
            #pragma unroll
            for (int half = 0; half < 2; half++) {
                int nt = 2 * ks + half;
                #pragma unroll
                for (int rp = 0; rp < 2; rp++) {
                    uint32_t hp, lp;
                    split2(acc[nt][2*rp], acc[nt][2*rp+1], hp, lp);
                    aPh[ks][half*2 + rp] = hp;
                    aPl[ks][half*2 + rp] = lp;
                }
            }
        }

        #pragma unroll
        for (int s = 0; s < 4; s++) {
            uint32_t kB = ((uint32_t)(s * 32) + bkb) ^ xr;
            uint32_t bV[4][4];
            #pragma unroll
            for (int p = 0; p < 4; p++) LDSM4(bV[p], sV + boffs[p] + kB);
            #pragma unroll
            for (int p = 0; p < 4; p++) {
                MMA16816(o[2*p],   aPh[s], bV[p][0], bV[p][1]);
                MMA16816(o[2*p+1], aPh[s], bV[p][2], bV[p][3]);
                MMA16816(o[2*p],   aPl[s], bV[p][0], bV[p][1]);
                MMA16816(o[2*p+1], aPl[s], bV[p][2], bV[p][3]);
            }
        }
    }

    // epilogue: normalize + split fp16 into O-projection input [M, E]
    const int b = bh >> 4, h = bh & 15;
    float il0 = 1.0f / lv[0], il1 = 1.0f / lv[1];
    const int row0 = q0 + wm + g;
    #pragma unroll
    for (int nt = 0; nt < 8; nt++) {
        int col = h * 64 + nt * 8 + tq;
        uint32_t hp, lp;
        size_t i0 = (size_t)(b * Ss + row0) * Ee + col;
        split2(o[nt][0] * il0, o[nt][1] * il0, hp, lp);
        *(uint32_t*)(xh + i0) = hp;
        *(uint32_t*)(xl + i0) = lp;
        size_t i1 = (size_t)(b * Ss + row0 + 8) * Ee + col;
        split2(o[nt][2] * il1, o[nt][3] * il1, hp, lp);
        *(uint32_t*)(xh + i1) = hp;
        *(uint32_t*)(xl + i1) = lp;
    }
}

// ---------------------------------------------------------------------------
extern "C" void kernel_launch(void* const* d_in, const int* in_sizes, int n_in,
                              void* d_out, int out_size)
{
    (void)in_sizes; (void)n_in; (void)out_size;
    const float* query = (const float*)d_in[0];
    const float* key   = (const float*)d_in[1];
    const float* value = (const float*)d_in[2];
    const float* Wq = (const float*)d_in[3];
    const float* bq = (const float*)d_in[4];
    const float* Wk = (const float*)d_in[5];
    const float* bk = (const float*)d_in[6];
    const float* Wv = (const float*)d_in[7];
    const float* bv = (const float*)d_in[8];
    const float* Wo = (const float*)d_in[9];
    const float* bo = (const float*)d_in[10];
    float* out = (float*)d_out;

    float *vp, *ct, *st;
    __half *xh, *xl, *wh, *qh, *ql, *kh, *vth;
    cudaGetSymbolAddress((void**)&vp,  g_v);
    cudaGetSymbolAddress((void**)&ct,  g_cos);
    cudaGetSymbolAddress((void**)&st,  g_sin);
    cudaGetSymbolAddress((void**)&xh,  g_xh3);
    cudaGetSymbolAddress((void**)&xl,  g_xl3);
    cudaGetSymbolAddress((void**)&wh,  g_wh4);
    cudaGetSymbolAddress((void**)&qh,  g_qh);
    cudaGetSymbolAddress((void**)&ql,  g_ql);
    cudaGetSymbolAddress((void**)&kh,  g_kh);
    cudaGetSymbolAddress((void**)&vth, g_vth);

    cudaFuncSetAttribute(tgemm_qkv,
                         cudaFuncAttributeMaxDynamicSharedMemorySize, TG_SMEM);
    cudaFuncSetAttribute(tgemm_o,
                         cudaFuncAttributeMaxDynamicSharedMemorySize, TG_SMEM);
    cudaFuncSetAttribute(flash_mma,
                         cudaFuncAttributeMaxDynamicSharedMemorySize, FL_SMEM);

    const int WBLK = (Ee * Ee / 4) / 256;   // 1024
    const int XBLK = (Mm * Ee / 4) / 256;   // 4096
    dim3 gg(Ee / 128, Mm / 128);            // (8, 32)

    rope_table_kernel<<<(Ss * 32) / 256, 256>>>(ct, st);

    split3_kernel<<<dim3(XBLK, 3), 256>>>(query, key, value, xh, xl, Mm * Ee / 4);
    round4W_kernel<<<dim3(WBLK, 4), 256>>>(Wq, Wk, Wv, Wo, wh, Ee * Ee / 4);

    // fused QKV projection (Q: rope+split; K: rope hi-only; V: fp32)
    tgemm_qkv<<<dim3(Ee / 128, Mm / 128, 3), 256, TG_SMEM>>>(bq, bk, bv, vp, ct, st);

    vconvert<<<dim3(Ss / 64, Bb * Hh), 256>>>(vp, vth);

    // flash writes split fp16 straight into O-projection input (slot 0)
    flash_mma<<<dim3(Ss / 128, Bb * Hh), 256, FL_SMEM>>>(qh, ql, kh, vth, xh, xl);

    tgemm_o<<<gg, 256, TG_SMEM>>>(bo, out);
}

// round 15
// speedup vs baseline: 1.4604x; 1.0614x over previous
#include <cuda_runtime.h>
#include <cuda_fp16.h>
#include <math.h>
#include <stdint.h>

#define Bb 2
#define Ss 2048
#define Ee 1024
#define Hh 16
#define Dd 64
#define Mm (Bb*Ss)   // 4096

// Scratch (allocation-free rule: __device__ globals)
__device__ float g_cos[Ss*32];
__device__ float g_sin[Ss*32];
__device__ __half g_xh3[3*Mm*Ee];
__device__ __half g_xl3[3*Mm*Ee];
__device__ __half g_wh4[4*Ee*Ee];
__device__ __half g_qh[Bb*Hh*Ss*Dd];
__device__ __half g_ql[Bb*Hh*Ss*Dd];
__device__ __half g_kh[Bb*Hh*Ss*Dd];
__device__ __half g_vh[Bb*Hh*Ss*Dd];

// ---------------------------------------------------------------------------
// Helpers (plain sm_80-class PTX only: mma.sync / ldmatrix / cp.async)
// ---------------------------------------------------------------------------
__device__ __forceinline__ uint32_t smem_to_u32(const void* p) {
    uint32_t a;
    asm("{ .reg .u64 t; cvta.to.shared.u64 t, %1; cvt.u32.u64 %0, t; }" : "=r"(a) : "l"(p));
    return a;
}
#define CP_ASYNC16(dst, src) \
    asm volatile("cp.async.cg.shared.global [%0], [%1], 16;" :: "r"(dst), "l"(src))
#define CP_ASYNC_COMMIT() asm volatile("cp.async.commit_group;" ::: "memory")
#define CP_ASYNC_WAIT0()  asm volatile("cp.async.wait_group 0;" ::: "memory")
#define SWZ128(o) ((o) ^ (((o) >> 3) & 0x70))

#define LDSM4(r, addr) \
    asm volatile("ldmatrix.sync.aligned.m8n8.x4.shared.b16 {%0,%1,%2,%3}, [%4];" \
        : "=r"((r)[0]), "=r"((r)[1]), "=r"((r)[2]), "=r"((r)[3]) : "r"(addr))

#define LDSM4T(r, addr) \
    asm volatile("ldmatrix.sync.aligned.m8n8.x4.trans.shared.b16 {%0,%1,%2,%3}, [%4];" \
        : "=r"((r)[0]), "=r"((r)[1]), "=r"((r)[2]), "=r"((r)[3]) : "r"(addr))

#define MMA16816(c, a, b0, b1) \
    asm volatile("mma.sync.aligned.m16n8k16.row.col.f32.f16.f16.f32 " \
        "{%0,%1,%2,%3},{%4,%5,%6,%7},{%8,%9},{%0,%1,%2,%3};" \
        : "+f"((c)[0]), "+f"((c)[1]), "+f"((c)[2]), "+f"((c)[3]) \
        : "r"((a)[0]), "r"((a)[1]), "r"((a)[2]), "r"((a)[3]), "r"(b0), "r"(b1))

__device__ __forceinline__ uint32_t h2u(__half2 h) {
    return *reinterpret_cast<uint32_t*>(&h);
}
__device__ __forceinline__ uint32_t f16pack(float a, float b) {
    __half2 h = __floats2half2_rn(a, b);
    return h2u(h);
}
// split pair into fp16 hi + fp16 lo residual
__device__ __forceinline__ void split2(float a, float b, uint32_t& h, uint32_t& l) {
    __half2 hh = __floats2half2_rn(a, b);
    float fa = __half2float(__low2half(hh)), fb = __half2float(__high2half(hh));
    __half2 ll = __floats2half2_rn(a - fa, b - fb);
    h = h2u(hh);
    l = h2u(ll);
}

// fast e^x on FMA pipe
__device__ __forceinline__ float fexp(float x) {
    x = fmaxf(x, -87.0f);
    float z = x * 1.4426950408889634f;
    float t = z + 12582912.0f;
    float n = t - 12582912.0f;
    float f = z - n;
    float p = 1.3333558146e-3f;
    p = fmaf(p, f, 9.6181291907e-3f);
    p = fmaf(p, f, 5.5504108664e-2f);
    p = fmaf(p, f, 2.4022650696e-1f);
    p = fmaf(p, f, 6.9314718056e-1f);
    p = fmaf(p, f, 1.0f);
    float sc = __uint_as_float((__float_as_uint(t) << 23) + 0x3F800000u);
    return p * sc;
}

// ---------------------------------------------------------------------------
// Batched splits / rounds
// ---------------------------------------------------------------------------
__global__ __launch_bounds__(256)
void split3_kernel(const float* __restrict__ s0, const float* __restrict__ s1,
                   const float* __restrict__ s2, __half* __restrict__ hi,
                   __half* __restrict__ lo, int elems4)
{
    int z = blockIdx.y;
    const float* x = (z == 0) ? s0 : (z == 1) ? s1 : s2;
    int i = blockIdx.x * 256 + threadIdx.x;
    float4 v = ((const float4*)x)[i];
    uint32_t h01, l01, h23, l23;
    split2(v.x, v.y, h01, l01);
    split2(v.z, v.w, h23, l23);
    ((uint2*)hi)[(size_t)z * elems4 + i] = make_uint2(h01, h23);
    ((uint2*)lo)[(size_t)z * elems4 + i] = make_uint2(l01, l23);
}

// round 4 weight matrices to single fp16
__global__ __launch_bounds__(256)
void round4W_kernel(const float* __restrict__ s0, const float* __restrict__ s1,
                    const float* __restrict__ s2, const float* __restrict__ s3,
                    __half* __restrict__ hi, int elems4)
{
    int z = blockIdx.y;
    const float* x = (z == 0) ? s0 : (z == 1) ? s1 : (z == 2) ? s2 : s3;
    int i = blockIdx.x * 256 + threadIdx.x;
    float4 v = ((const float4*)x)[i];
    ((uint2*)hi)[(size_t)z * elems4 + i] =
        make_uint2(f16pack(v.x, v.y), f16pack(v.z, v.w));
}

// ---------------------------------------------------------------------------
// HMMA GEMM body, fp16 2-term (A split hi+lo, B single fp16).
// Single-stage, K-chunk 64 (SW128), 256 threads, 8 warps 4m x 2n (warp 32x64).
// mode 0: fp32 row-major + bias  (O projection)
// mode 2: bias + RoPE + fp16 scatter [B,H,S,D]  (Q: hi+lo, K: hi only)
// mode 3: bias + fp16 scatter [B,H,S,D]  (V)
// ---------------------------------------------------------------------------
#define TG_SMEM 49152

__device__ __forceinline__
void tgemm_body(uint32_t sb, const __half* Ahp, const __half* Alp,
                const __half* Bhp,
                const float* bias, float* outf,
                __half* dh, __half* dl,
                const float* ct, const float* st,
                int mode, int m0, int n0)
{
    const int tid = threadIdx.x;
    const int lane = tid & 31, wid = tid >> 5;
    const int wm = (wid >> 1) * 32, wn = (wid & 1) * 64;

    const uint32_t sA  = sb;
    const uint32_t sAl = sb + 16384;
    const uint32_t sB  = sb + 32768;

    float acc[2][8][4];
    #pragma unroll
    for (int mt = 0; mt < 2; mt++)
        #pragma unroll
        for (int nt = 0; nt < 8; nt++)
            #pragma unroll
            for (int r = 0; r < 4; r++) acc[mt][nt][r] = 0.f;

    const int lr = lane & 15;
    const uint32_t akb = (lane >> 4) * 16;
    const uint32_t xrA = (uint32_t)(lr & 7) << 4;
    const int brow = (lane & 7) + ((lane >> 1) & 8);
    const uint32_t bkb = (uint32_t)(lane & 8) * 2;
    const uint32_t xrB = (uint32_t)(lane & 7) << 4;

    uint32_t aoff[2], boff[4];
    #pragma unroll
    for (int mt = 0; mt < 2; mt++) aoff[mt] = (uint32_t)(wm + mt * 16 + lr) * 128;
    #pragma unroll
    for (int p = 0; p < 4; p++)    boff[p]  = (uint32_t)(wn + p * 16 + brow) * 128;

    const char* srcs[3] = {(const char*)Ahp, (const char*)Alp, (const char*)Bhp};
    const uint32_t dsts[3] = {sA, sAl, sB};
    const int r0s[3] = {m0, m0, n0};

    for (int kc = 0; kc < 16; kc++) {
        if (kc) __syncthreads();
        #pragma unroll
        for (int arr = 0; arr < 3; arr++) {
            #pragma unroll
            for (int i = 0; i < 4; i++) {
                int p = i * 256 + tid;
                int r = p >> 3, c = (p & 7) * 16;
                uint32_t dst = dsts[arr] + SWZ128((uint32_t)(r * 128 + c));
                const char* src = srcs[arr] + ((size_t)(r0s[arr] + r)) * 2048
                                  + kc * 128 + c;
                CP_ASYNC16(dst, src);
            }
        }
        CP_ASYNC_COMMIT();
        CP_ASYNC_WAIT0();
        __syncthreads();

        #pragma unroll
        for (int s = 0; s < 4; s++) {
            const uint32_t kA = ((uint32_t)(s * 32) + akb) ^ xrA;
            const uint32_t kB = ((uint32_t)(s * 32) + bkb) ^ xrB;

            uint32_t ah[2][4], al[2][4], bh[4][4];
            #pragma unroll
            for (int mt = 0; mt < 2; mt++) LDSM4(ah[mt], sA  + aoff[mt] + kA);
            #pragma unroll
            for (int mt = 0; mt < 2; mt++) LDSM4(al[mt], sAl + aoff[mt] + kA);
            #pragma unroll
            for (int p = 0; p < 4; p++)    LDSM4(bh[p],  sB  + boff[p] + kB);

            #pragma unroll
            for (int mt = 0; mt < 2; mt++)
                #pragma unroll
                for (int nt = 0; nt < 8; nt++) {
                    MMA16816(acc[mt][nt], ah[mt], bh[nt>>1][(nt&1)*2], bh[nt>>1][(nt&1)*2+1]);
                    MMA16816(acc[mt][nt], al[mt], bh[nt>>1][(nt&1)*2], bh[nt>>1][(nt&1)*2+1]);
                }
        }
    }

    const int g = lane >> 2, t = (lane & 3) * 2;

    if (mode == 2) {
        // bias + RoPE + fp16 scatter to [B,H,S,D]; lo only if dl != nullptr
        const int hh = (n0 + wn) >> 6;
        #pragma unroll
        for (int mt = 0; mt < 2; mt++) {
            #pragma unroll
            for (int nt = 0; nt < 4; nt++) {
                const int j = nt * 8 + t;            // pair index 0..31 (even)
                float b1a = bias[hh*64 + j],      b1b = bias[hh*64 + j + 1];
                float b2a = bias[hh*64 + j + 32], b2b = bias[hh*64 + j + 33];
                #pragma unroll
                for (int rr = 0; rr < 2; rr++) {
                    int m = m0 + wm + mt * 16 + g + rr * 8;
                    int b = m >> 11, s = m & 2047;
                    float2 cs = *(const float2*)(ct + s * 32 + j);
                    float2 sn = *(const float2*)(st + s * 32 + j);
                    float x1a = acc[mt][nt][rr*2]     + b1a;
                    float x1b = acc[mt][nt][rr*2+1]   + b1b;
                    float x2a = acc[mt][nt+4][rr*2]   + b2a;
                    float x2b = acc[mt][nt+4][rr*2+1] + b2b;
                    float r1a = x1a*cs.x - x2a*sn.x, r2a = x2a*cs.x + x1a*sn.x;
                    float r1b = x1b*cs.y - x2b*sn.y, r2b = x2b*cs.y + x1b*sn.y;
                    size_t base = ((size_t)(b * Hh + hh) * Ss + s) * Dd;
                    if (dl) {
                        uint32_t h1, l1, h2, l2;
                        split2(r1a, r1b, h1, l1);
                        split2(r2a, r2b, h2, l2);
                        *(uint32_t*)(dh + base + j)      = h1;
                        *(uint32_t*)(dl + base + j)      = l1;
                        *(uint32_t*)(dh + base + j + 32) = h2;
                        *(uint32_t*)(dl + base + j + 32) = l2;
                    } else {
                        *(uint32_t*)(dh + base + j)      = f16pack(r1a, r1b);
                        *(uint32_t*)(dh + base + j + 32) = f16pack(r2a, r2b);
                    }
                }
            }
        }
    } else if (mode == 3) {
        // bias + fp16 scatter to [B,H,S,D] (V)
        #pragma unroll
        for (int mt = 0; mt < 2; mt++) {
            #pragma unroll
            for (int nt = 0; nt < 8; nt++) {
                int n = n0 + wn + nt * 8 + t;
                float b0v = bias[n], b1v = bias[n + 1];
                int h = n >> 6, d0 = n & 63;
                #pragma unroll
                for (int rr = 0; rr < 2; rr++) {
                    int mr = m0 + wm + mt * 16 + g + rr * 8;
                    int b = mr >> 11, s = mr & 2047;
                    size_t base = ((size_t)(b * Hh + h) * Ss + s) * Dd + d0;
                    *(uint32_t*)(dh + base) =
                        f16pack(acc[mt][nt][rr*2] + b0v, acc[mt][nt][rr*2+1] + b1v);
                }
            }
        }
    } else {
        #pragma unroll
        for (int mt = 0; mt < 2; mt++) {
            #pragma unroll
            for (int nt = 0; nt < 8; nt++) {
                int m = m0 + wm + mt * 16 + g;
                int n = n0 + wn + nt * 8 + t;
                float b0v = bias[n], b1v = bias[n + 1];
                #pragma unroll
                for (int rr = 0; rr < 2; rr++) {
                    int mr = m + rr * 8;
                    float2 val = make_float2(acc[mt][nt][rr*2] + b0v,
                                             acc[mt][nt][rr*2+1] + b1v);
                    *(float2*)(outf + (size_t)mr * Ee + n) = val;
                }
            }
        }
    }
}

// Fused QKV projection: z=0 Q (rope+split), z=1 K (rope hi), z=2 V (fp16).
__global__ __launch_bounds__(256, 2)
void tgemm_qkv(const float* __restrict__ bq, const float* __restrict__ bk,
               const float* __restrict__ bv,
               const float* __restrict__ ct, const float* __restrict__ st)
{
    extern __shared__ char smem[];
    uint32_t sb = smem_to_u32(smem);
    const int z = blockIdx.z;
    const size_t xo = (size_t)z * Mm * Ee, wo = (size_t)z * Ee * Ee;
    const float* bias = (z == 0) ? bq : (z == 1) ? bk : bv;
    __half* dh = (z == 0) ? g_qh : (z == 1) ? g_kh : g_vh;
    __half* dl = (z == 0) ? g_ql : nullptr;
    tgemm_body(sb, g_xh3 + xo, g_xl3 + xo, g_wh4 + wo,
               bias, nullptr, dh, dl, ct, st,
               (z == 2) ? 3 : 2, blockIdx.y * 128, blockIdx.x * 128);
}

// O projection: X from slot 0 (written by flash), W from slot 3.
__global__ __launch_bounds__(256, 2)
void tgemm_o(const float* __restrict__ bias, float* __restrict__ out)
{
    extern __shared__ char smem[];
    uint32_t sb = smem_to_u32(smem);
    tgemm_body(sb, g_xh3, g_xl3, g_wh4 + (size_t)3 * Ee * Ee,
               bias, out, nullptr, nullptr, nullptr, nullptr,
               0, blockIdx.y * 128, blockIdx.x * 128);
}

// ---------------------------------------------------------------------------
// RoPE table
// ---------------------------------------------------------------------------
__global__ __launch_bounds__(256)
void rope_table_kernel(float* __restrict__ cosT, float* __restrict__ sinT)
{
    int idx = blockIdx.x * 256 + threadIdx.x;
    int j = idx & 31;
    int s = idx >> 5;
    double inv = exp(-((double)(2 * j) / 64.0) * log(10000.0));
    double sd, cd;
    sincos((double)s * inv, &sd, &cd);
    cosT[idx] = (float)cd;
    sinT[idx] = (float)sd;
}

// ---------------------------------------------------------------------------
// Flash attention, fp16 (Q 2-term, K/V/P single term), causal.
// Block = 128 q rows, 8 warps (warp m16 x n64). KV tile 64. smem 48KB.
// V consumed untransposed [t][d] via ldmatrix.trans for the PV B-operand.
// Epilogue writes split fp16 into O-projection input (g_xh3/g_xl3 slot 0).
// ---------------------------------------------------------------------------
#define FL_SMEM 49152

__global__ __launch_bounds__(256)
void flash_mma(const __half* __restrict__ qhp, const __half* __restrict__ qlp,
               const __half* __restrict__ khp, const __half* __restrict__ vhp,
               __half* __restrict__ xh, __half* __restrict__ xl)
{
    extern __shared__ char smem[];
    uint32_t sb = smem_to_u32(smem);
    const uint32_t sQh = sb,          sQl = sb + 16384;
    const uint32_t sK  = sb + 32768,  sV  = sb + 40960;

    const int tid = threadIdx.x, lane = tid & 31, wid = tid >> 5;
    const int qt = (int)gridDim.x - 1 - (int)blockIdx.x;   // heavy tiles first
    const int bh = blockIdx.y;
    const int q0 = qt * 128;
    const int wm = wid * 16;

    {
        const char* gq  = (const char*)qhp + ((size_t)(bh * Ss + q0)) * 128;
        const char* gql = (const char*)qlp + ((size_t)(bh * Ss + q0)) * 128;
        #pragma unroll
        for (int i = 0; i < 4; i++) {
            int p = i * 256 + tid;
            int r = p >> 3, c = (p & 7) * 16;
            uint32_t o1 = SWZ128((uint32_t)(r * 128 + c));
            CP_ASYNC16(sQh + o1, gq  + (size_t)r * 128 + c);
            CP_ASYNC16(sQl + o1, gql + (size_t)r * 128 + c);
        }
        CP_ASYNC_COMMIT(); CP_ASYNC_WAIT0();
    }
    __syncthreads();

    const uint32_t xr  = (uint32_t)(lane & 7) << 4;
    const uint32_t akb = (uint32_t)(lane >> 4) * 16;
    const uint32_t arow = (uint32_t)(wm + (lane & 15)) * 128;
    uint32_t aQh[4][4], aQl[4][4];
    #pragma unroll
    for (int s = 0; s < 4; s++) {
        uint32_t kA = ((uint32_t)(s * 32) + akb) ^ xr;
        LDSM4(aQh[s], sQh + arow + kA);
        LDSM4(aQl[s], sQl + arow + kA);
    }

    const int brow = (lane & 7) + ((lane >> 1) & 8);
    const uint32_t bkb = (uint32_t)(lane & 8) * 2;
    uint32_t boffs[4];
    #pragma unroll
    for (int p = 0; p < 4; p++) boffs[p] = (uint32_t)(p * 16 + brow) * 128;

    // trans-LDSM lane addressing for V [t][d]:
    //   matrix m = lane>>3: row group (m&1)*8, byte col group (m>>1)*16
    const int vm = lane >> 3;
    const uint32_t vrow16 = (uint32_t)((vm & 1) * 8 + (lane & 7));
    const uint32_t vcb0 = (uint32_t)((vm >> 1) * 16);

    float o[8][4];
    #pragma unroll
    for (int nt = 0; nt < 8; nt++)
        #pragma unroll
        for (int r = 0; r < 4; r++) o[nt][r] = 0.f;
    float mv[2] = {-1e30f, -1e30f}, lv[2] = {0.f, 0.f};

    const int g = lane >> 2, tq = (lane & 3) * 2;
    const int ntiles = 2 * qt + 2;

    for (int it = 0; it < ntiles; it++) {
        const int kv0 = it * 64;
        __syncthreads();
        {
            const char* gk = (const char*)khp + ((size_t)(bh * Ss + kv0)) * 128;
            const char* gv = (const char*)vhp + ((size_t)(bh * Ss + kv0)) * 128;
            #pragma unroll
            for (int i = 0; i < 2; i++) {
                int p = i * 256 + tid;
                int r = p >> 3, c = (p & 7) * 16;
                uint32_t o1 = SWZ128((uint32_t)(r * 128 + c));
                CP_ASYNC16(sK + o1, gk + (size_t)r * 128 + c);
                CP_ASYNC16(sV + o1, gv + (size_t)r * 128 + c);
            }
            CP_ASYNC_COMMIT(); CP_ASYNC_WAIT0();
        }
        __syncthreads();

        float acc[8][4];
        #pragma unroll
        for (int nt = 0; nt < 8; nt++)
            #pragma unroll
            for (int r = 0; r < 4; r++) acc[nt][r] = 0.f;

        #pragma unroll
        for (int s = 0; s < 4; s++) {
            uint32_t kB = ((uint32_t)(s * 32) + bkb) ^ xr;
            uint32_t bK[4][4];
            #pragma unroll
            for (int p = 0; p < 4; p++) LDSM4(bK[p], sK + boffs[p] + kB);
            #pragma unroll
            for (int p = 0; p < 4; p++) {
                MMA16816(acc[2*p],   aQh[s], bK[p][0], bK[p][1]);
                MMA16816(acc[2*p+1], aQh[s], bK[p][2], bK[p][3]);
                MMA16816(acc[2*p],   aQl[s], bK[p][0], bK[p][1]);
                MMA16816(acc[2*p+1], aQl[s], bK[p][2], bK[p][3]);
            }
        }

        const int row0 = q0 + wm + g;
        if (it >= 2 * qt) {
            #pragma unroll
            for (int nt = 0; nt < 8; nt++) {
                int col = kv0 + nt * 8 + tq;
                #pragma unroll
                for (int r = 0; r < 4; r++) {
                    int cc = col + (r & 1);
                    int rr = row0 + (r >= 2 ? 8 : 0);
                    acc[nt][r] = (cc > rr) ? -1e30f : acc[nt][r] * 0.125f;
                }
            }
        } else {
            #pragma unroll
            for (int nt = 0; nt < 8; nt++)
                #pragma unroll
                for (int r = 0; r < 4; r++) acc[nt][r] *= 0.125f;
        }

        #pragma unroll
        for (int h = 0; h < 2; h++) {
            float rmax = -1e30f;
            #pragma unroll
            for (int nt = 0; nt < 8; nt++)
                rmax = fmaxf(rmax, fmaxf(acc[nt][2*h], acc[nt][2*h+1]));
            rmax = fmaxf(rmax, __shfl_xor_sync(0xffffffffu, rmax, 1));
            rmax = fmaxf(rmax, __shfl_xor_sync(0xffffffffu, rmax, 2));
            float mnew = fmaxf(mv[h], rmax);
            float fac = fexp(mv[h] - mnew);
            float rs = 0.f;
            #pragma unroll
            for (int nt = 0; nt < 8; nt++) {
                acc[nt][2*h]   = fexp(acc[nt][2*h]   - mnew);
                acc[nt][2*h+1] = fexp(acc[nt][2*h+1] - mnew);
                rs += acc[nt][2*h] + acc[nt][2*h+1];
            }
            rs += __shfl_xor_sync(0xffffffffu, rs, 1);
            rs += __shfl_xor_sync(0xffffffffu, rs, 2);
            lv[h] = lv[h] * fac + rs;
            mv[h] = mnew;
            #pragma unroll
            for (int nt = 0; nt < 8; nt++) { o[nt][2*h] *= fac; o[nt][2*h+1] *= fac; }
        }

        // P -> fp16 A-fragments (single term)
        uint32_t aPh[4][4];
        #pragma unroll
        for (int ks = 0; ks < 4; ks++) {
            #pragma unroll
            for (int half = 0; half < 2; half++) {
                int nt = 2 * ks + half;
                #pragma unroll
                for (int rp = 0; rp < 2; rp++)
                    aPh[ks][half*2 + rp] = f16pack(acc[nt][2*rp], acc[nt][2*rp+1]);
            }
        }

        // O += P V  (V via trans-LDSM from [t][d] tile)
        #pragma unroll
        for (int s = 0; s < 4; s++) {
            uint32_t bV[4][4];
            #pragma unroll
            for (int p = 0; p < 4; p++) {
                uint32_t addr = sV + ((uint32_t)(s * 16) + vrow16) * 128
                              + (((uint32_t)(p * 32) + vcb0) ^ xr);
                LDSM4T(bV[p], addr);
            }
            #pragma unroll
            for (int p = 0; p < 4; p++) {
                MMA16816(o[2*p],   aPh[s], bV[p][0], bV[p][1]);
                MMA16816(o[2*p+1], aPh[s], bV[p][2], bV[p][3]);
            }
        }
    }

    // epilogue: normalize + split fp16 into O-projection input [M, E]
    const int b = bh >> 4, h = bh & 15;
    float il0 = 1.0f / lv[0], il1 = 1.0f / lv[1];
    const int row0 = q0 + wm + g;
    #pragma unroll
    for (int nt = 0; nt < 8; nt++) {
        int col = h * 64 + nt * 8 + tq;
        uint32_t hp, lp;
        size_t i0 = (size_t)(b * Ss + row0) * Ee + col;
        split2(o[nt][0] * il0, o[nt][1] * il0, hp, lp);
        *(uint32_t*)(xh + i0) = hp;
        *(uint32_t*)(xl + i0) = lp;
        size_t i1 = (size_t)(b * Ss + row0 + 8) * Ee + col;
        split2(o[nt][2] * il1, o[nt][3] * il1, hp, lp);
        *(uint32_t*)(xh + i1) = hp;
        *(uint32_t*)(xl + i1) = lp;
    }
}

// ---------------------------------------------------------------------------
extern "C" void kernel_launch(void* const* d_in, const int* in_sizes, int n_in,
                              void* d_out, int out_size)
{
    (void)in_sizes; (void)n_in; (void)out_size;
    const float* query = (const float*)d_in[0];
    const float* key   = (const float*)d_in[1];
    const float* value = (const float*)d_in[2];
    const float* Wq = (const float*)d_in[3];
    const float* bq = (const float*)d_in[4];
    const float* Wk = (const float*)d_in[5];
    const float* bk = (const float*)d_in[6];
    const float* Wv = (const float*)d_in[7];
    const float* bv = (const float*)d_in[8];
    const float* Wo = (const float*)d_in[9];
    const float* bo = (const float*)d_in[10];
    float* out = (float*)d_out;

    float *ct, *st;
    __half *xh, *xl, *wh, *qh, *ql, *kh, *vh;
    cudaGetSymbolAddress((void**)&ct,  g_cos);
    cudaGetSymbolAddress((void**)&st,  g_sin);
    cudaGetSymbolAddress((void**)&xh,  g_xh3);
    cudaGetSymbolAddress((void**)&xl,  g_xl3);
    cudaGetSymbolAddress((void**)&wh,  g_wh4);
    cudaGetSymbolAddress((void**)&qh,  g_qh);
    cudaGetSymbolAddress((void**)&ql,  g_ql);
    cudaGetSymbolAddress((void**)&kh,  g_kh);
    cudaGetSymbolAddress((void**)&vh,  g_vh);

    cudaFuncSetAttribute(tgemm_qkv,
                         cudaFuncAttributeMaxDynamicSharedMemorySize, TG_SMEM);
    cudaFuncSetAttribute(tgemm_o,
                         cudaFuncAttributeMaxDynamicSharedMemorySize, TG_SMEM);
    cudaFuncSetAttribute(flash_mma,
                         cudaFuncAttributeMaxDynamicSharedMemorySize, FL_SMEM);

    const int WBLK = (Ee * Ee / 4) / 256;   // 1024
    const int XBLK = (Mm * Ee / 4) / 256;   // 4096
    dim3 gg(Ee / 128, Mm / 128);            // (8, 32)

    rope_table_kernel<<<(Ss * 32) / 256, 256>>>(ct, st);

    split3_kernel<<<dim3(XBLK, 3), 256>>>(query, key, value, xh, xl, Mm * Ee / 4);
    round4W_kernel<<<dim3(WBLK, 4), 256>>>(Wq, Wk, Wv, Wo, wh, Ee * Ee / 4);

    // fused QKV projection (Q: rope+split; K: rope hi-only; V: fp16 direct)
    tgemm_qkv<<<dim3(Ee / 128, Mm / 128, 3), 256, TG_SMEM>>>(bq, bk, bv, ct, st);

    // flash writes split fp16 straight into O-projection input (slot 0)
    flash_mma<<<dim3(Ss / 128, Bb * Hh), 256, FL_SMEM>>>(qh, ql, kh, vh, xh, xl);

    tgemm_o<<<gg, 256, TG_SMEM>>>(bo, out);
}